// round 5
// baseline (speedup 1.0000x reference)
#include <cuda_runtime.h>

// Problem constants (fixed shapes)
#define DD    2048      // hidden dim
#define NTOK  16384     // B*T = 4*4096
#define NE    18        // 16 expert rows + 2 group rows
#define THRV  0.15f
#define ROWU  512       // ulonglong2 (16B units) per row: 2048 floats / 4

// Global scratch (no cudaMalloc allowed). Zero at module load; the last
// block of each launch resets them -> deterministic across graph replays.
__device__ int g_counts[16];
__device__ unsigned int g_done;

// Packed dual-fp32 FMA, operands kept as u64 end-to-end (no float2
// marshaling MOVs in SASS).
__device__ __forceinline__ unsigned long long ffma2u(
    unsigned long long a, unsigned long long b, unsigned long long c) {
    unsigned long long d;
    asm("fma.rn.f32x2 %0, %1, %2, %3;" : "=l"(d) : "l"(a), "l"(b), "l"(c));
    return d;
}

__device__ __forceinline__ float pairsum(unsigned long long v) {
    float2 f = *reinterpret_cast<float2*>(&v);
    return f.x + f.y;
}

// One expert sweep for a 128B d-chunk: 18 W loads (deduped to 1 wavefront
// each across the 4 lane-groups) + 72 FFMA2.
__device__ __forceinline__ void expert_step(
    const ulonglong2* __restrict__ Weu, const ulonglong2* __restrict__ Wgu,
    int q, ulonglong2 xa, ulonglong2 xb,
    unsigned long long* accA, unsigned long long* accB)
{
    #pragma unroll
    for (int e = 0; e < NE; e++) {
        const ulonglong2* wr = (e < 16) ? (Weu + (size_t)e * ROWU)
                                        : (Wgu + (size_t)(e - 16) * ROWU);
        ulonglong2 w = __ldg(wr + q);
        accA[e] = ffma2u(xa.x, w.x, accA[e]);
        accA[e] = ffma2u(xa.y, w.y, accA[e]);
        accB[e] = ffma2u(xb.x, w.x, accB[e]);
        accB[e] = ffma2u(xb.y, w.y, accB[e]);
    }
}

// 128 threads = 4 warps. Each warp: 4 groups of 8 lanes, each group owns
// 2 tokens -> 8 tokens/warp, 32 tokens/block. Grid = 512 blocks = 1 wave.
__global__ void __launch_bounds__(128, 4) egr_router_kernel(
    const float* __restrict__ x,
    const float* __restrict__ We,    // [16, D]
    const float* __restrict__ Wg,    // [2, D]
    float* __restrict__ out)
{
    __shared__ int hist[16];
    __shared__ bool isLast;
    const int tid = threadIdx.x;
    if (tid < 16) hist[tid] = 0;
    __syncthreads();

    const int warp = tid >> 5;
    const int lane = tid & 31;
    const int grp  = lane >> 3;          // 0..3 (token-pair group)
    const int r    = lane & 7;           // lane within group
    const int tokA = (blockIdx.x * 4 + warp) * 8 + 2 * grp;  // tokens tokA, tokA+1

    const ulonglong2* xA  = reinterpret_cast<const ulonglong2*>(x) + (size_t)tokA * ROWU;
    const ulonglong2* xB  = xA + ROWU;
    const ulonglong2* Weu = reinterpret_cast<const ulonglong2*>(We);
    const ulonglong2* Wgu = reinterpret_cast<const ulonglong2*>(Wg);

    unsigned long long accA[NE], accB[NE];
    #pragma unroll
    for (int e = 0; e < NE; e++) { accA[e] = 0ull; accB[e] = 0ull; }

    // 64 iterations; iteration i covers 32 floats (128B): unit offset q = i*8 + r.
    // Ring-2 prefetch of x (streaming, .cs) -> ~2 iterations of DRAM latency cover.
    ulonglong2 pa0 = __ldcs(xA + r),     pb0 = __ldcs(xB + r);
    ulonglong2 pa1 = __ldcs(xA + 8 + r), pb1 = __ldcs(xB + 8 + r);

    #pragma unroll 1
    for (int i = 0; i < 64; i += 2) {
        ulonglong2 xa = pa0, xb = pb0;
        if (i + 2 < 64) { pa0 = __ldcs(xA + (i + 2) * 8 + r);
                          pb0 = __ldcs(xB + (i + 2) * 8 + r); }
        expert_step(Weu, Wgu, i * 8 + r, xa, xb, accA, accB);

        xa = pa1; xb = pb1;
        if (i + 3 < 64) { pa1 = __ldcs(xA + (i + 3) * 8 + r);
                          pb1 = __ldcs(xB + (i + 3) * 8 + r); }
        expert_step(Weu, Wgu, (i + 1) * 8 + r, xa, xb, accA, accB);
    }

    // Reduce over the 8 lanes of each group (xor on bits 0-2 stays in-group)
    float redA[NE], redB[NE];
    #pragma unroll
    for (int e = 0; e < NE; e++) {
        float vA = pairsum(accA[e]);
        float vB = pairsum(accB[e]);
        #pragma unroll
        for (int off = 4; off; off >>= 1) {
            vA += __shfl_xor_sync(0xffffffffu, vA, off);
            vB += __shfl_xor_sync(0xffffffffu, vB, off);
        }
        redA[e] = vA; redB[e] = vB;
    }

    // Lanes r=0 / r=1 of each group route token tokA / tokA+1
    if (r < 2) {
        float s[NE];
        #pragma unroll
        for (int e = 0; e < NE; e++) s[e] = (r == 0) ? redA[e] : redB[e];
        const int tok = tokA + r;

        const float g0 = 1.f / (1.f + expf(-s[16]));
        const float g1 = 1.f / (1.f + expf(-s[17]));

        // --- Group A: experts 0..7, top-1 softmax prob ---
        float ma = s[0]; int ai = 0;
        #pragma unroll
        for (int j = 1; j < 8; j++) if (s[j] > ma) { ma = s[j]; ai = j; }
        float dena = 0.f;
        #pragma unroll
        for (int j = 0; j < 8; j++) dena += expf(s[j] - ma);
        const float aw = 1.f / dena;

        // --- Group B: experts 8..11 ---
        float mb = s[8]; int bi = 0;
        #pragma unroll
        for (int j = 1; j < 4; j++) if (s[8 + j] > mb) { mb = s[8 + j]; bi = j; }
        float denb = 0.f;
        #pragma unroll
        for (int j = 0; j < 4; j++) denb += expf(s[8 + j] - mb);
        const float bact = (g0 > THRV) ? 1.f : 0.f;
        const float bw = (1.f / denb) * g0 * bact;

        // --- Group C: experts 12..15, top-2 (first-occurrence tie-break) ---
        float b1 = s[12]; int i1 = 0;
        float b2 = -3.402823466e+38f; int i2 = 0;
        #pragma unroll
        for (int j = 1; j < 4; j++) {
            float v = s[12 + j];
            if (v > b1)      { b2 = b1; i2 = i1; b1 = v; i1 = j; }
            else if (v > b2) { b2 = v;  i2 = j; }
        }
        float denc = 0.f;
        #pragma unroll
        for (int j = 0; j < 4; j++) denc += expf(s[12 + j] - b1);
        const float cact = (g1 > THRV) ? 1.f : 0.f;
        const float cg   = g1 * cact;
        const float cw0  = (1.f / denc) * cg;
        const float cw1  = (expf(b2 - b1) / denc) * cg;

        // --- Normalize & write ---
        const float inv = 1.f / (aw + bw + cw0 + cw1 + 1e-8f);
        float* ow = out + (size_t)tok * 6;
        ow[0] = aw  * inv;
        ow[1] = bw  * inv;
        ow[2] = cw0 * inv;
        ow[3] = cw1 * inv;
        ow[4] = 0.f;
        ow[5] = 0.f;

        float* oi = out + (size_t)NTOK * 6 + (size_t)tok * 6;
        oi[0] = (float)ai;
        oi[1] = (float)(8 + bi);
        oi[2] = (float)(12 + i1);
        oi[3] = (float)(12 + i2);
        oi[4] = 0.f;
        oi[5] = 0.f;

        atomicAdd(&hist[ai],      1);
        atomicAdd(&hist[8 + bi],  1);
        atomicAdd(&hist[12 + i1], 1);
        atomicAdd(&hist[12 + i2], 1);
    }

    __syncthreads();
    if (tid < 16) {
        atomicAdd(&g_counts[tid], hist[tid]);
        __threadfence();                 // publish before the done-ticket
    }
    __syncthreads();
    if (tid == 0) {
        unsigned v = atomicAdd(&g_done, 1u);
        isLast = (v == gridDim.x - 1);
    }
    __syncthreads();

    // Last block computes the aux loss and resets global scratch
    if (isLast && tid == 0) {
        __threadfence();                 // acquire all blocks' counts
        const float total = 6.0f * (float)NTOK;   // counts.sum(): 6 slots/token
        const float u  = 1.0f / 16.0f;
        const float lu = logf(u);
        float aux = 0.f;
        #pragma unroll
        for (int e = 0; e < 16; e++) {
            // two zero-pads per token land in bin 0 of jnp.bincount
            float c = (float)g_counts[e] + (e == 0 ? 2.0f * (float)NTOK : 0.0f);
            aux += u * (lu - logf(c / total));
            g_counts[e] = 0;            // reset for next replay
        }
        out[(size_t)2 * NTOK * 6] = aux * 0.01f;
        g_done = 0;                      // reset ticket for next replay
    }
}

extern "C" void kernel_launch(void* const* d_in, const int* in_sizes, int n_in,
                              void* d_out, int out_size) {
    const float* x  = (const float*)d_in[0];   // (4,4096,2048) f32
    const float* We = (const float*)d_in[1];   // (16,2048) f32
    const float* Wg = (const float*)d_in[2];   // (2,2048) f32
    float* out = (float*)d_out;                // weights | indices | aux

    egr_router_kernel<<<NTOK / 32, 128>>>(x, We, Wg, out);
}

// round 6
// speedup vs baseline: 1.4526x; 1.4526x over previous
#include <cuda_runtime.h>

// Problem constants (fixed shapes)
#define DD      2048        // hidden dim
#define NTOK    16384       // B*T
#define NE      18          // 16 expert rows + 2 group rows
#define THRV    0.15f
#define ROWU    512         // ulonglong2 (16B units) per W/x row
#define CHUNK_U 64          // ulonglong2 per chunk per row (256 floats)
#define NCHUNK  8           // ROWU / CHUNK_U
#define WS_BUF  (NE * CHUNK_U)   // 1152 ulonglong2 per smem buffer

// Global scratch (no cudaMalloc). Zeroed at load; last block resets after use.
__device__ int g_counts[16];
__device__ unsigned int g_done;

// Packed dual-fp32 FMA, operands kept as u64 end-to-end.
__device__ __forceinline__ unsigned long long ffma2u(
    unsigned long long a, unsigned long long b, unsigned long long c) {
    unsigned long long d;
    asm("fma.rn.f32x2 %0, %1, %2, %3;" : "=l"(d) : "l"(a), "l"(b), "l"(c));
    return d;
}

__device__ __forceinline__ float pairsum(unsigned long long v) {
    float2 f = *reinterpret_cast<float2*>(&v);
    return f.x + f.y;
}

// One 16B d-slice for 2 tokens x 18 experts, W from shared memory.
// qs = j*8 + r; all 4 lane-groups read the same 128B run -> conflict-free.
__device__ __forceinline__ void expert_step_s(
    const ulonglong2* __restrict__ wb, int qs,
    ulonglong2 xa, ulonglong2 xb,
    unsigned long long* accA, unsigned long long* accB)
{
    #pragma unroll
    for (int e = 0; e < NE; e++) {
        ulonglong2 w = wb[e * CHUNK_U + qs];          // LDS.128 broadcast
        accA[e] = ffma2u(xa.x, w.x, accA[e]);
        accA[e] = ffma2u(xa.y, w.y, accA[e]);
        accB[e] = ffma2u(xb.x, w.x, accB[e]);
        accB[e] = ffma2u(xb.y, w.y, accB[e]);
    }
}

// 128 threads = 4 warps. Warp = 4 groups of 8 lanes, each group 2 tokens
// -> 8 tokens/warp, 32 tokens/block, 512 blocks (single wave, 4 blocks/SM).
__global__ void __launch_bounds__(128, 4) egr_router_kernel(
    const float* __restrict__ x,
    const float* __restrict__ We,    // [16, D]
    const float* __restrict__ Wg,    // [2, D]
    float* __restrict__ out)
{
    __shared__ ulonglong2 ws[2 * WS_BUF];   // 36864 B double-buffered W chunk
    __shared__ int hist[16];
    __shared__ bool isLast;

    const int tid = threadIdx.x;
    if (tid < 16) hist[tid] = 0;

    const int warp = tid >> 5;
    const int lane = tid & 31;
    const int grp  = lane >> 3;          // 0..3 token-pair group
    const int r    = lane & 7;           // lane within group
    const int tokA = (blockIdx.x * 4 + warp) * 8 + 2 * grp;

    const ulonglong2* xA  = reinterpret_cast<const ulonglong2*>(x) + (size_t)tokA * ROWU;
    const ulonglong2* xB  = xA + ROWU;
    const ulonglong2* Weu = reinterpret_cast<const ulonglong2*>(We);
    const ulonglong2* Wgu = reinterpret_cast<const ulonglong2*>(Wg);

    // Staging source for this thread: 9 elements/chunk, idx = tid + 128k.
    // row = idx/64 (expert), u = idx%64 (unit within chunk).
    // Stage chunk 0 into buffer 0.
    #pragma unroll
    for (int k = 0; k < 9; k++) {
        const int idx = tid + (k << 7);
        const int row = idx >> 6, u = idx & 63;
        const ulonglong2* src = (row < 16) ? (Weu + (size_t)row * ROWU)
                                           : (Wgu + (size_t)(row - 16) * ROWU);
        ws[idx] = __ldg(src + u);
    }

    unsigned long long accA[NE], accB[NE];
    #pragma unroll
    for (int e = 0; e < NE; e++) { accA[e] = 0ull; accB[e] = 0ull; }

    // x ring-2 prefetch (streaming; global iteration gi covers units gi*8+r)
    ulonglong2 pa0 = __ldcs(xA + r),     pb0 = __ldcs(xB + r);
    ulonglong2 pa1 = __ldcs(xA + 8 + r), pb1 = __ldcs(xB + 8 + r);

    __syncthreads();                      // chunk 0 staged

    #pragma unroll 1
    for (int c = 0; c < NCHUNK; c++) {
        // Stage next chunk into the other buffer (LDGs overlap compute below)
        if (c + 1 < NCHUNK) {
            const int boff = ((c + 1) & 1) * WS_BUF;
            const int coff = (c + 1) * CHUNK_U;
            #pragma unroll 3
            for (int k = 0; k < 9; k++) {
                const int idx = tid + (k << 7);
                const int row = idx >> 6, u = idx & 63;
                const ulonglong2* src = (row < 16) ? (Weu + (size_t)row * ROWU)
                                                   : (Wgu + (size_t)(row - 16) * ROWU);
                ws[boff + idx] = __ldg(src + coff + u);
            }
        }

        const ulonglong2* wb = ws + (c & 1) * WS_BUF;

        // 8 sub-iterations of 32 floats; gi = c*8 + j
        #pragma unroll
        for (int j = 0; j < 8; j += 2) {
            const int gi = c * 8 + j;
            ulonglong2 xa = pa0, xb = pb0;
            if (gi + 2 < 64) { pa0 = __ldcs(xA + (gi + 2) * 8 + r);
                               pb0 = __ldcs(xB + (gi + 2) * 8 + r); }
            expert_step_s(wb, j * 8 + r, xa, xb, accA, accB);

            xa = pa1; xb = pb1;
            if (gi + 3 < 64) { pa1 = __ldcs(xA + (gi + 3) * 8 + r);
                               pb1 = __ldcs(xB + (gi + 3) * 8 + r); }
            expert_step_s(wb, (j + 1) * 8 + r, xa, xb, accA, accB);
        }

        __syncthreads();   // staged buffer complete + old buffer consumed
    }

    // Reduce over the 8 lanes of each group (xor 4/2/1 stays in-group)
    float redA[NE], redB[NE];
    #pragma unroll
    for (int e = 0; e < NE; e++) {
        float vA = pairsum(accA[e]);
        float vB = pairsum(accB[e]);
        #pragma unroll
        for (int off = 4; off; off >>= 1) {
            vA += __shfl_xor_sync(0xffffffffu, vA, off);
            vB += __shfl_xor_sync(0xffffffffu, vB, off);
        }
        redA[e] = vA; redB[e] = vB;
    }

    // Lanes r=0 / r=1 of each group route token tokA / tokA+1
    if (r < 2) {
        float s[NE];
        #pragma unroll
        for (int e = 0; e < NE; e++) s[e] = (r == 0) ? redA[e] : redB[e];
        const int tok = tokA + r;

        const float g0 = 1.f / (1.f + expf(-s[16]));
        const float g1 = 1.f / (1.f + expf(-s[17]));

        // Group A: experts 0..7, top-1 softmax prob
        float ma = s[0]; int ai = 0;
        #pragma unroll
        for (int j = 1; j < 8; j++) if (s[j] > ma) { ma = s[j]; ai = j; }
        float dena = 0.f;
        #pragma unroll
        for (int j = 0; j < 8; j++) dena += expf(s[j] - ma);
        const float aw = 1.f / dena;

        // Group B: experts 8..11
        float mb = s[8]; int bi = 0;
        #pragma unroll
        for (int j = 1; j < 4; j++) if (s[8 + j] > mb) { mb = s[8 + j]; bi = j; }
        float denb = 0.f;
        #pragma unroll
        for (int j = 0; j < 4; j++) denb += expf(s[8 + j] - mb);
        const float bact = (g0 > THRV) ? 1.f : 0.f;
        const float bw = (1.f / denb) * g0 * bact;

        // Group C: experts 12..15, top-2 (first-occurrence tie-break)
        float b1 = s[12]; int i1 = 0;
        float b2 = -3.402823466e+38f; int i2 = 0;
        #pragma unroll
        for (int j = 1; j < 4; j++) {
            float v = s[12 + j];
            if (v > b1)      { b2 = b1; i2 = i1; b1 = v; i1 = j; }
            else if (v > b2) { b2 = v;  i2 = j; }
        }
        float denc = 0.f;
        #pragma unroll
        for (int j = 0; j < 4; j++) denc += expf(s[12 + j] - b1);
        const float cact = (g1 > THRV) ? 1.f : 0.f;
        const float cg   = g1 * cact;
        const float cw0  = (1.f / denc) * cg;
        const float cw1  = (expf(b2 - b1) / denc) * cg;

        // Normalize & write
        const float inv = 1.f / (aw + bw + cw0 + cw1 + 1e-8f);
        float* ow = out + (size_t)tok * 6;
        ow[0] = aw  * inv;
        ow[1] = bw  * inv;
        ow[2] = cw0 * inv;
        ow[3] = cw1 * inv;
        ow[4] = 0.f;
        ow[5] = 0.f;

        float* oi = out + (size_t)NTOK * 6 + (size_t)tok * 6;
        oi[0] = (float)ai;
        oi[1] = (float)(8 + bi);
        oi[2] = (float)(12 + i1);
        oi[3] = (float)(12 + i2);
        oi[4] = 0.f;
        oi[5] = 0.f;

        atomicAdd(&hist[ai],      1);
        atomicAdd(&hist[8 + bi],  1);
        atomicAdd(&hist[12 + i1], 1);
        atomicAdd(&hist[12 + i2], 1);
    }

    __syncthreads();
    if (tid < 16) {
        atomicAdd(&g_counts[tid], hist[tid]);
        __threadfence();                 // publish before the done-ticket
    }
    __syncthreads();
    if (tid == 0) {
        unsigned v = atomicAdd(&g_done, 1u);
        isLast = (v == gridDim.x - 1);
    }
    __syncthreads();

    // Last block computes the aux loss and resets global scratch
    if (isLast && tid == 0) {
        __threadfence();
        const float total = 6.0f * (float)NTOK;
        const float u  = 1.0f / 16.0f;
        const float lu = logf(u);
        float aux = 0.f;
        #pragma unroll
        for (int e = 0; e < 16; e++) {
            float c = (float)g_counts[e] + (e == 0 ? 2.0f * (float)NTOK : 0.0f);
            aux += u * (lu - logf(c / total));
            g_counts[e] = 0;            // reset for next replay
        }
        out[(size_t)2 * NTOK * 6] = aux * 0.01f;
        g_done = 0;
    }
}

extern "C" void kernel_launch(void* const* d_in, const int* in_sizes, int n_in,
                              void* d_out, int out_size) {
    const float* x  = (const float*)d_in[0];   // (4,4096,2048) f32
    const float* We = (const float*)d_in[1];   // (16,2048) f32
    const float* Wg = (const float*)d_in[2];   // (2,2048) f32
    float* out = (float*)d_out;                // weights | indices | aux

    egr_router_kernel<<<NTOK / 32, 128>>>(x, We, Wg, out);
}

// round 9
// speedup vs baseline: 1.5111x; 1.0403x over previous
#include <cuda_runtime.h>

// Problem constants (fixed shapes)
#define DD      2048        // hidden dim
#define NTOK    16384       // B*T
#define NE      18          // 16 expert rows + 2 group rows
#define TE      9           // experts per lane-group
#define TT      4           // tokens per lane-group
#define THRV    0.15f
#define ROWU    512         // ulonglong2 (16B units) per W/x row
#define CHUNK_U 64          // ulonglong2 per chunk per row (256 floats)
#define NCHUNK  8           // ROWU / CHUNK_U
#define WS_BUF  (NE * CHUNK_U)   // 1152 ulonglong2 per smem buffer

// Global scratch (no cudaMalloc). Zeroed at load; last block resets after use.
__device__ int g_counts[16];
__device__ unsigned int g_done;

// Packed dual-fp32 FMA, operands kept as u64 end-to-end.
__device__ __forceinline__ unsigned long long ffma2u(
    unsigned long long a, unsigned long long b, unsigned long long c) {
    unsigned long long d;
    asm("fma.rn.f32x2 %0, %1, %2, %3;" : "=l"(d) : "l"(a), "l"(b), "l"(c));
    return d;
}

__device__ __forceinline__ float pairsum(unsigned long long v) {
    float2 f = *reinterpret_cast<float2*>(&v);
    return f.x + f.y;
}

// 128 threads = 4 warps. Warp = 4 groups of 8 lanes.
// Groups 0,1 share tokens [wb..wb+3] and split experts (0-8 / 9-17);
// groups 2,3 likewise for tokens [wb+4..wb+7]. 8 tokens/warp, 32/block.
__global__ void __launch_bounds__(128, 4) egr_router_kernel(
    const float* __restrict__ x,
    const float* __restrict__ We,    // [16, D]
    const float* __restrict__ Wg,    // [2, D]
    float* __restrict__ out)
{
    __shared__ ulonglong2 ws[2 * WS_BUF];   // 36864 B double-buffered W chunk
    __shared__ float sc[32][NE + 1];        // per-block token scores (padded)
    __shared__ int hist[16];
    __shared__ bool isLast;

    const int tid = threadIdx.x;
    if (tid < 16) hist[tid] = 0;

    const int warp  = tid >> 5;
    const int lane  = tid & 31;
    const int grp   = lane >> 3;         // 0..3
    const int r     = lane & 7;          // lane within group
    const int ebase = (grp & 1) * TE;    // expert base: 0 or 9
    const int tloc  = warp * 8 + (grp >> 1) * 4;        // local token base
    const int tokB  = blockIdx.x * 32 + tloc;           // global token base

    const ulonglong2* xr  = reinterpret_cast<const ulonglong2*>(x) + (size_t)tokB * ROWU;
    const ulonglong2* Weu = reinterpret_cast<const ulonglong2*>(We);
    const ulonglong2* Wgu = reinterpret_cast<const ulonglong2*>(Wg);

    // Stage W chunk 0 into buffer 0 (9 x 16B per thread per chunk)
    #pragma unroll
    for (int k = 0; k < 9; k++) {
        const int idx = tid + (k << 7);
        const int row = idx >> 6, u = idx & 63;
        const ulonglong2* src = (row < 16) ? (Weu + (size_t)row * ROWU)
                                           : (Wgu + (size_t)(row - 16) * ROWU);
        ws[idx] = __ldg(src + u);
    }

    unsigned long long acc[TE][TT];
    #pragma unroll
    for (int i = 0; i < TE; i++)
        #pragma unroll
        for (int t = 0; t < TT; t++) acc[i][t] = 0ull;

    // x current-step values (ring-1 prefetch, streaming)
    ulonglong2 xa[TT];
    #pragma unroll
    for (int t = 0; t < TT; t++) xa[t] = __ldcs(xr + (size_t)t * ROWU + r);

    __syncthreads();                      // W chunk 0 staged

    #pragma unroll 1
    for (int c = 0; c < NCHUNK; c++) {
        // Stage next W chunk into the other buffer (overlaps compute)
        if (c + 1 < NCHUNK) {
            const int boff = ((c + 1) & 1) * WS_BUF;
            const int coff = (c + 1) * CHUNK_U;
            #pragma unroll 3
            for (int k = 0; k < 9; k++) {
                const int idx = tid + (k << 7);
                const int row = idx >> 6, u = idx & 63;
                const ulonglong2* src = (row < 16) ? (Weu + (size_t)row * ROWU)
                                                   : (Wgu + (size_t)(row - 16) * ROWU);
                ws[boff + idx] = __ldg(src + coff + u);
            }
        }

        const ulonglong2* wb = ws + (c & 1) * WS_BUF + (size_t)ebase * CHUNK_U;

        // 8 steps of 32 floats per row; global step gi = c*8 + j
        #pragma unroll
        for (int j = 0; j < 8; j++) {
            // Prefetch next step's x (batched LDGs, in flight during FMA)
            ulonglong2 pa[TT];
            const int gi = c * 8 + j;
            if (j < 7 || c + 1 < NCHUNK) {
                #pragma unroll
                for (int t = 0; t < TT; t++)
                    pa[t] = __ldcs(xr + (size_t)t * ROWU + (gi + 1) * 8 + r);
            }

            #pragma unroll
            for (int i = 0; i < TE; i++) {
                ulonglong2 w = wb[i * CHUNK_U + j * 8 + r];   // LDS.128
                #pragma unroll
                for (int t = 0; t < TT; t++) {
                    acc[i][t] = ffma2u(xa[t].x, w.x, acc[i][t]);
                    acc[i][t] = ffma2u(xa[t].y, w.y, acc[i][t]);
                }
            }

            #pragma unroll
            for (int t = 0; t < TT; t++) xa[t] = pa[t];
        }

        __syncthreads();   // next buffer staged + old buffer consumed
    }

    // Reduce each of the 36 partials over the 8 lanes of the group.
    // Results valid on lane r==0 of each group; all indexing compile-time.
    float red[TE][TT];
    #pragma unroll
    for (int i = 0; i < TE; i++)
        #pragma unroll
        for (int t = 0; t < TT; t++) {
            float v = pairsum(acc[i][t]);
            v += __shfl_xor_sync(0xffffffffu, v, 4);
            v += __shfl_xor_sync(0xffffffffu, v, 2);
            v += __shfl_xor_sync(0xffffffffu, v, 1);
            red[i][t] = v;
        }

    if (r == 0) {
        #pragma unroll
        for (int t = 0; t < TT; t++)
            #pragma unroll
            for (int i = 0; i < TE; i++)
                sc[tloc + t][ebase + i] = red[i][t];
    }
    __syncthreads();

    // 32 router threads: one token each
    if (tid < 32) {
        float s[NE];
        #pragma unroll
        for (int e = 0; e < NE; e++) s[e] = sc[tid][e];
        const int tok = blockIdx.x * 32 + tid;

        const float g0 = 1.f / (1.f + expf(-s[16]));
        const float g1 = 1.f / (1.f + expf(-s[17]));

        // Group A: experts 0..7, top-1 softmax prob
        float ma = s[0]; int ai = 0;
        #pragma unroll
        for (int j = 1; j < 8; j++) if (s[j] > ma) { ma = s[j]; ai = j; }
        float dena = 0.f;
        #pragma unroll
        for (int j = 0; j < 8; j++) dena += expf(s[j] - ma);
        const float aw = 1.f / dena;

        // Group B: experts 8..11
        float mb = s[8]; int bi = 0;
        #pragma unroll
        for (int j = 1; j < 4; j++) if (s[8 + j] > mb) { mb = s[8 + j]; bi = j; }
        float denb = 0.f;
        #pragma unroll
        for (int j = 0; j < 4; j++) denb += expf(s[8 + j] - mb);
        const float bact = (g0 > THRV) ? 1.f : 0.f;
        const float bw = (1.f / denb) * g0 * bact;

        // Group C: experts 12..15, top-2 (first-occurrence tie-break)
        float b1 = s[12]; int i1 = 0;
        float b2 = -3.402823466e+38f; int i2 = 0;
        #pragma unroll
        for (int j = 1; j < 4; j++) {
            float v = s[12 + j];
            if (v > b1)      { b2 = b1; i2 = i1; b1 = v; i1 = j; }
            else if (v > b2) { b2 = v;  i2 = j; }
        }
        float denc = 0.f;
        #pragma unroll
        for (int j = 0; j < 4; j++) denc += expf(s[12 + j] - b1);
        const float cact = (g1 > THRV) ? 1.f : 0.f;
        const float cg   = g1 * cact;
        const float cw0  = (1.f / denc) * cg;
        const float cw1  = (expf(b2 - b1) / denc) * cg;

        // Normalize & write
        const float inv = 1.f / (aw + bw + cw0 + cw1 + 1e-8f);
        float* ow = out + (size_t)tok * 6;
        ow[0] = aw  * inv;
        ow[1] = bw  * inv;
        ow[2] = cw0 * inv;
        ow[3] = cw1 * inv;
        ow[4] = 0.f;
        ow[5] = 0.f;

        float* oi = out + (size_t)NTOK * 6 + (size_t)tok * 6;
        oi[0] = (float)ai;
        oi[1] = (float)(8 + bi);
        oi[2] = (float)(12 + i1);
        oi[3] = (float)(12 + i2);
        oi[4] = 0.f;
        oi[5] = 0.f;

        atomicAdd(&hist[ai],      1);
        atomicAdd(&hist[8 + bi],  1);
        atomicAdd(&hist[12 + i1], 1);
        atomicAdd(&hist[12 + i2], 1);
    }

    __syncthreads();
    if (tid < 16) {
        atomicAdd(&g_counts[tid], hist[tid]);
        __threadfence();                 // publish before the done-ticket
    }
    __syncthreads();
    if (tid == 0) {
        unsigned v = atomicAdd(&g_done, 1u);
        isLast = (v == gridDim.x - 1);
    }
    __syncthreads();

    // Last block computes the aux loss and resets global scratch
    if (isLast && tid == 0) {
        __threadfence();
        const float total = 6.0f * (float)NTOK;
        const float u  = 1.0f / 16.0f;
        const float lu = logf(u);
        float aux = 0.f;
        #pragma unroll
        for (int e = 0; e < 16; e++) {
            float c = (float)g_counts[e] + (e == 0 ? 2.0f * (float)NTOK : 0.0f);
            aux += u * (lu - logf(c / total));
            g_counts[e] = 0;            // reset for next replay
        }
        out[(size_t)2 * NTOK * 6] = aux * 0.01f;
        g_done = 0;
    }
}

extern "C" void kernel_launch(void* const* d_in, const int* in_sizes, int n_in,
                              void* d_out, int out_size) {
    const float* x  = (const float*)d_in[0];   // (4,4096,2048) f32
    const float* We = (const float*)d_in[1];   // (16,2048) f32
    const float* Wg = (const float*)d_in[2];   // (2,2048) f32
    float* out = (float*)d_out;                // weights | indices | aux

    egr_router_kernel<<<NTOK / 32, 128>>>(x, We, Wg, out);
}

// round 11
// speedup vs baseline: 2.0168x; 1.3347x over previous
#include <cuda_runtime.h>

// Problem constants (fixed shapes)
#define DD    2048       // hidden dim
#define NTOK  16384      // B*T
#define NE    18         // 16 expert rows + 2 group rows
#define TE    9          // experts per half-warp
#define TT    4          // tokens per warp
#define THRV  0.15f
#define ROWU  512        // ulonglong2 (16B units) per W/x row
#define CU    16         // ulonglong2 per chunk per row (64 floats)
#define NCH   32         // chunks over D
#define RING  4          // cp.async ring depth
#define TOKB  16         // tokens per block (4 warps x 4 tokens)

// Global scratch (no cudaMalloc). Zeroed at load; last block resets after use.
__device__ int g_counts[16];
__device__ unsigned int g_done;

__device__ __forceinline__ unsigned long long ffma2u(
    unsigned long long a, unsigned long long b, unsigned long long c) {
    unsigned long long d;
    asm("fma.rn.f32x2 %0, %1, %2, %3;" : "=l"(d) : "l"(a), "l"(b), "l"(c));
    return d;
}

__device__ __forceinline__ float pairsum(unsigned long long v) {
    float2 f = *reinterpret_cast<float2*>(&v);
    return f.x + f.y;
}

__device__ __forceinline__ void cp16(void* s, const void* g) {
    unsigned sa = (unsigned)__cvta_generic_to_shared(s);
    asm volatile("cp.async.cg.shared.global [%0], [%1], 16;"
                 :: "r"(sa), "l"(g) : "memory");
}
#define CP_COMMIT()  asm volatile("cp.async.commit_group;" ::: "memory")
#define CP_WAIT(n)   asm volatile("cp.async.wait_group %0;" :: "n"(n) : "memory")

// 128 threads = 4 warps; warp = 2 halves of 16 lanes.
// Halves share the warp's 4 tokens and split experts (0-8 / 9-17).
__global__ void __launch_bounds__(128, 4) egr_router_kernel(
    const float* __restrict__ x,
    const float* __restrict__ We,    // [16, D]
    const float* __restrict__ Wg,    // [2, D]
    float* __restrict__ out)
{
    __shared__ ulonglong2 wsl[RING][NE][CU];    // 18432 B  W ring
    __shared__ ulonglong2 xsl[RING][TOKB][CU];  // 16384 B  x ring
    __shared__ float sc[TOKB][NE + 1];
    __shared__ int hist[16];
    __shared__ bool isLast;

    const int tid  = threadIdx.x;
    if (tid < 16) hist[tid] = 0;

    const int warp  = tid >> 5;
    const int lane  = tid & 31;
    const int h     = lane >> 4;         // half: 0/1 -> expert split
    const int r     = lane & 15;         // 16B-unit within chunk
    const int ebase = h * TE;
    const int tw    = warp * TT;         // local token base

    const ulonglong2* Xu  = reinterpret_cast<const ulonglong2*>(x)
                            + (size_t)blockIdx.x * TOKB * ROWU;
    const ulonglong2* Weu = reinterpret_cast<const ulonglong2*>(We);
    const ulonglong2* Wgu = reinterpret_cast<const ulonglong2*>(Wg);

    // ---- async stage of chunk c into ring slot c&3 ----
    auto stage = [&](int c) {
        const int s = c & (RING - 1);
        // W: 288 16B units
        #pragma unroll
        for (int k = 0; k < 3; k++) {
            const int idx = tid + (k << 7);
            if (idx < NE * CU) {
                const int row = idx >> 4, u = idx & 15;
                const ulonglong2* src = (row < 16)
                    ? (Weu + (size_t)row * ROWU)
                    : (Wgu + (size_t)(row - 16) * ROWU);
                cp16(&wsl[s][row][u], src + c * CU + u);
            }
        }
        // x: 256 16B units
        #pragma unroll
        for (int k = 0; k < 2; k++) {
            const int idx = tid + (k << 7);
            const int tok = idx >> 4, u = idx & 15;
            cp16(&xsl[s][tok][u], Xu + (size_t)tok * ROWU + c * CU + u);
        }
        CP_COMMIT();
    };

    unsigned long long acc[TE][TT];
    #pragma unroll
    for (int i = 0; i < TE; i++)
        #pragma unroll
        for (int t = 0; t < TT; t++) acc[i][t] = 0ull;

    stage(0); stage(1); stage(2);        // 3 groups in flight

    #pragma unroll 1
    for (int c = 0; c < NCH; c++) {
        CP_WAIT(2);                      // chunk c's group complete (this thread)
        __syncthreads();                 // ...and visible from all threads

        if (c + 3 < NCH) stage(c + 3);   // refill (slot was consumed at c-1)
        else CP_COMMIT();                // keep group count uniform

        const int s = c & (RING - 1);
        ulonglong2 xa[TT];
        #pragma unroll
        for (int t = 0; t < TT; t++) xa[t] = xsl[s][tw + t][r];

        #pragma unroll
        for (int i = 0; i < TE; i++) {
            ulonglong2 w = wsl[s][ebase + i][r];    // LDS.128
            #pragma unroll
            for (int t = 0; t < TT; t++) {
                acc[i][t] = ffma2u(xa[t].x, w.x, acc[i][t]);
                acc[i][t] = ffma2u(xa[t].y, w.y, acc[i][t]);
            }
        }
    }
    CP_WAIT(0);                          // drain empties before exit path

    // Reduce each partial over the 16 lanes of the half (stays within half)
    #pragma unroll
    for (int i = 0; i < TE; i++)
        #pragma unroll
        for (int t = 0; t < TT; t++) {
            float v = pairsum(acc[i][t]);
            v += __shfl_xor_sync(0xffffffffu, v, 8);
            v += __shfl_xor_sync(0xffffffffu, v, 4);
            v += __shfl_xor_sync(0xffffffffu, v, 2);
            v += __shfl_xor_sync(0xffffffffu, v, 1);
            if (r == 0) sc[tw + t][ebase + i] = v;
        }
    __syncthreads();

    // 16 router threads: one token each
    if (tid < 16) {
        float s[NE];
        #pragma unroll
        for (int e = 0; e < NE; e++) s[e] = sc[tid][e];
        const int tok = blockIdx.x * TOKB + tid;

        const float g0 = 1.f / (1.f + expf(-s[16]));
        const float g1 = 1.f / (1.f + expf(-s[17]));

        // Group A: experts 0..7, top-1 softmax prob
        float ma = s[0]; int ai = 0;
        #pragma unroll
        for (int j = 1; j < 8; j++) if (s[j] > ma) { ma = s[j]; ai = j; }
        float dena = 0.f;
        #pragma unroll
        for (int j = 0; j < 8; j++) dena += expf(s[j] - ma);
        const float aw = 1.f / dena;

        // Group B: experts 8..11
        float mb = s[8]; int bi = 0;
        #pragma unroll
        for (int j = 1; j < 4; j++) if (s[8 + j] > mb) { mb = s[8 + j]; bi = j; }
        float denb = 0.f;
        #pragma unroll
        for (int j = 0; j < 4; j++) denb += expf(s[8 + j] - mb);
        const float bact = (g0 > THRV) ? 1.f : 0.f;
        const float bw = (1.f / denb) * g0 * bact;

        // Group C: experts 12..15, top-2 (first-occurrence tie-break)
        float b1 = s[12]; int i1 = 0;
        float b2 = -3.402823466e+38f; int i2 = 0;
        #pragma unroll
        for (int j = 1; j < 4; j++) {
            float v = s[12 + j];
            if (v > b1)      { b2 = b1; i2 = i1; b1 = v; i1 = j; }
            else if (v > b2) { b2 = v;  i2 = j; }
        }
        float denc = 0.f;
        #pragma unroll
        for (int j = 0; j < 4; j++) denc += expf(s[12 + j] - b1);
        const float cact = (g1 > THRV) ? 1.f : 0.f;
        const float cg   = g1 * cact;
        const float cw0  = (1.f / denc) * cg;
        const float cw1  = (expf(b2 - b1) / denc) * cg;

        // Normalize & write
        const float inv = 1.f / (aw + bw + cw0 + cw1 + 1e-8f);
        float* ow = out + (size_t)tok * 6;
        ow[0] = aw  * inv;
        ow[1] = bw  * inv;
        ow[2] = cw0 * inv;
        ow[3] = cw1 * inv;
        ow[4] = 0.f;
        ow[5] = 0.f;

        float* oi = out + (size_t)NTOK * 6 + (size_t)tok * 6;
        oi[0] = (float)ai;
        oi[1] = (float)(8 + bi);
        oi[2] = (float)(12 + i1);
        oi[3] = (float)(12 + i2);
        oi[4] = 0.f;
        oi[5] = 0.f;

        atomicAdd(&hist[ai],      1);
        atomicAdd(&hist[8 + bi],  1);
        atomicAdd(&hist[12 + i1], 1);
        atomicAdd(&hist[12 + i2], 1);
    }

    __syncthreads();
    if (tid < 16) {
        atomicAdd(&g_counts[tid], hist[tid]);
        __threadfence();                 // publish before the done-ticket
    }
    __syncthreads();
    if (tid == 0) {
        unsigned v = atomicAdd(&g_done, 1u);
        isLast = (v == gridDim.x - 1);
    }
    __syncthreads();

    // Last block computes the aux loss and resets global scratch
    if (isLast && tid == 0) {
        __threadfence();
        const float total = 6.0f * (float)NTOK;
        const float u  = 1.0f / 16.0f;
        const float lu = logf(u);
        float aux = 0.f;
        #pragma unroll
        for (int e = 0; e < 16; e++) {
            float c = (float)g_counts[e] + (e == 0 ? 2.0f * (float)NTOK : 0.0f);
            aux += u * (lu - logf(c / total));
            g_counts[e] = 0;            // reset for next replay
        }
        out[(size_t)2 * NTOK * 6] = aux * 0.01f;
        g_done = 0;
    }
}

extern "C" void kernel_launch(void* const* d_in, const int* in_sizes, int n_in,
                              void* d_out, int out_size) {
    const float* x  = (const float*)d_in[0];   // (4,4096,2048) f32
    const float* We = (const float*)d_in[1];   // (16,2048) f32
    const float* Wg = (const float*)d_in[2];   // (2,2048) f32
    float* out = (float*)d_out;                // weights | indices | aux

    egr_router_kernel<<<NTOK / TOKB, 128>>>(x, We, Wg, out);
}